// round 3
// baseline (speedup 1.0000x reference)
#include <cuda_runtime.h>
#include <math.h>

// Problem constants: x [T=8, B=32, C=128, H=32, W=32]
#define T_STEPS 8
#define BATCH   32
#define CH      128
#define HH      32
#define WW      32
#define NIMG    (T_STEPS * BATCH)        // 256 (T*B flattened, as in reference reshape)
#define PLANE   (HH * WW)                // 1024
#define NELEM   (BATCH * CH * PLANE)     // per-timestep element count: 4,194,304
#define TOTAL   (T_STEPS * NELEM)        // 33,554,432

// Scratch (no cudaMalloc allowed): two 128 MiB ping-pong buffers.
__device__ float g_spk[TOTAL];
__device__ float g_y[TOTAL];

// ---------------------------------------------------------------------------
// Multi-step IF neuron: v += x_t; s = (v >= 1); v *= (1 - s)   (hard reset)
// Elementwise over NELEM, sequential over T. Bit-exact match to the reference
// scan (same fp32 add order per element).
// ---------------------------------------------------------------------------
__global__ void if_kernel(const float* __restrict__ in, float* __restrict__ out) {
    int idx = blockIdx.x * blockDim.x + threadIdx.x;
    if (idx >= NELEM) return;
    float v = 0.0f;
#pragma unroll
    for (int t = 0; t < T_STEPS; ++t) {
        v += in[(size_t)t * NELEM + idx];
        float s = (v >= 1.0f) ? 1.0f : 0.0f;
        out[(size_t)t * NELEM + idx] = s;
        v *= (1.0f - s);
    }
}

// ---------------------------------------------------------------------------
// 3x3 conv (pad 1, no bias) + BN (inference affine) fused.
// Grid: (tb = 0..255, cog = 0..15). Block: 256 threads.
// Each block: one image, 8 output channels. Each thread: 4 spatial positions
// (p = tid + 256*i), 8 co accumulators (32 regs).
// Per input channel: stage 34x34 zero-padded plane + 8x9 weights in SMEM,
// hoist weights to registers, 9 window LDS + 72 FFMA per position.
// ---------------------------------------------------------------------------
__global__ void __launch_bounds__(256)
conv_bn_kernel(const float* __restrict__ in, const float* __restrict__ wgt,
               const float* __restrict__ gamma, const float* __restrict__ beta,
               const float* __restrict__ mean,  const float* __restrict__ var,
               float* __restrict__ out) {
    __shared__ float splane[34 * 34];   // zero-padded input plane
    __shared__ float swt[8 * 9];        // weights for 8 co, current ci

    const int tb     = blockIdx.x;
    const int cobase = blockIdx.y * 8;
    const int tid    = threadIdx.x;

    float acc[4][8];
#pragma unroll
    for (int i = 0; i < 4; ++i)
#pragma unroll
        for (int c = 0; c < 8; ++c) acc[i][c] = 0.0f;

    const float* ipbase = in + (size_t)tb * CH * PLANE;

    for (int ci = 0; ci < CH; ++ci) {
        __syncthreads();  // previous iteration's reads done before overwrite
        const float* ip = ipbase + (size_t)ci * PLANE;
        // Stage padded plane: 1156 elements via 5 strided passes of 256 threads.
#pragma unroll
        for (int l = 0; l < 5; ++l) {
            int idx = tid + l * 256;
            if (idx < 34 * 34) {
                int y = idx / 34;
                int x = idx - y * 34;
                float v = 0.0f;
                if (y >= 1 && y <= 32 && x >= 1 && x <= 32)
                    v = __ldg(&ip[(y - 1) * 32 + (x - 1)]);
                splane[idx] = v;
            }
        }
        // Stage weights w[cobase+co][ci][ky][kx]
        if (tid < 72) {
            int co = tid / 9;
            int k  = tid - co * 9;
            swt[tid] = wgt[((size_t)(cobase + co) * CH + ci) * 9 + k];
        }
        __syncthreads();

        // Hoist weights into registers (reused across 4 positions).
        float wr[72];
#pragma unroll
        for (int t = 0; t < 72; ++t) wr[t] = swt[t];

#pragma unroll
        for (int i = 0; i < 4; ++i) {
            int p = tid + (i << 8);
            int h = p >> 5;
            int x = p & 31;
            const float* sp = &splane[h * 34 + x];  // top-left of 3x3 window
            float a0 = sp[0],  a1 = sp[1],  a2 = sp[2];
            float b0 = sp[34], b1 = sp[35], b2 = sp[36];
            float c0 = sp[68], c1 = sp[69], c2 = sp[70];
#pragma unroll
            for (int co = 0; co < 8; ++co) {
                const float* wk = &wr[co * 9];
                acc[i][co] += a0 * wk[0] + a1 * wk[1] + a2 * wk[2]
                            + b0 * wk[3] + b1 * wk[4] + b2 * wk[5]
                            + c0 * wk[6] + c1 * wk[7] + c2 * wk[8];
            }
        }
    }

    // Fused BN epilogue: y*inv + (beta - mean*inv), inv = gamma/sqrt(var+eps)
#pragma unroll
    for (int co = 0; co < 8; ++co) {
        int cg = cobase + co;
        float inv  = gamma[cg] / sqrtf(var[cg] + 1e-5f);
        float bias = beta[cg] - mean[cg] * inv;
        float* op = out + ((size_t)tb * CH + cg) * PLANE;
#pragma unroll
        for (int i = 0; i < 4; ++i) {
            int p = tid + (i << 8);
            op[p] = acc[i][co] * inv + bias;
        }
    }
}

// ---------------------------------------------------------------------------
// Pipeline: if1(x)->spk ; conv1(spk)->y ; if2(y)->spk ; conv2(spk)->out
// All launches on the default stream (graph-capturable, no sync, no alloc).
// ---------------------------------------------------------------------------
extern "C" void kernel_launch(void* const* d_in, const int* in_sizes, int n_in,
                              void* d_out, int out_size) {
    const float* x  = (const float*)d_in[0];
    const float* w1 = (const float*)d_in[1];
    const float* g1 = (const float*)d_in[2];
    const float* b1 = (const float*)d_in[3];
    const float* m1 = (const float*)d_in[4];
    const float* v1 = (const float*)d_in[5];
    const float* w2 = (const float*)d_in[6];
    const float* g2 = (const float*)d_in[7];
    const float* b2 = (const float*)d_in[8];
    const float* m2 = (const float*)d_in[9];
    const float* v2 = (const float*)d_in[10];
    float* out = (float*)d_out;

    float *spk = nullptr, *y = nullptr;
    cudaGetSymbolAddress((void**)&spk, g_spk);   // pure query, capture-safe
    cudaGetSymbolAddress((void**)&y,   g_y);

    const int ifBlocks = (NELEM + 255) / 256;
    dim3 cgrid(NIMG, CH / 8);

    if_kernel<<<ifBlocks, 256>>>(x, spk);
    conv_bn_kernel<<<cgrid, 256>>>(spk, w1, g1, b1, m1, v1, y);
    if_kernel<<<ifBlocks, 256>>>(y, spk);
    conv_bn_kernel<<<cgrid, 256>>>(spk, w2, g2, b2, m2, v2, out);
}

// round 4
// speedup vs baseline: 2.6827x; 2.6827x over previous
#include <cuda_runtime.h>
#include <math.h>

// Problem constants: x [T=8, B=32, C=128, H=32, W=32]
#define T_STEPS 8
#define BATCH   32
#define CH      128
#define PLANE   1024                     // 32*32
#define NIMG    (T_STEPS * BATCH)        // 256
#define NELEM   (BATCH * CH * PLANE)     // 4,194,304
#define TOTAL   (T_STEPS * NELEM)        // 33,554,432

typedef unsigned long long ull;

// Scratch ping-pong buffers (no cudaMalloc allowed).
__device__ float g_spk[TOTAL];
__device__ float g_y[TOTAL];

// ---------------------------------------------------------------------------
// Packed fp32x2 helpers (Blackwell FFMA2 — only reachable via PTX)
// ---------------------------------------------------------------------------
__device__ __forceinline__ void fma2(ull& acc, ull a, ull b) {
    asm("fma.rn.f32x2 %0, %1, %2, %0;" : "+l"(acc) : "l"(a), "l"(b));
}
// {a.hi, b.lo} — middle tap pack
__device__ __forceinline__ ull mid2(ull a, ull b) {
    ull r;
    asm("{\n\t"
        ".reg .b32 xa, ya, xb, yb;\n\t"
        "mov.b64 {xa, ya}, %1;\n\t"
        "mov.b64 {xb, yb}, %2;\n\t"
        "mov.b64 %0, {ya, xb};\n\t"
        "}" : "=l"(r) : "l"(a), "l"(b));
    return r;
}
__device__ __forceinline__ void unpk(ull a, float& lo, float& hi) {
    asm("mov.b64 {%0, %1}, %2;" : "=f"(lo), "=f"(hi) : "l"(a));
}

// ---------------------------------------------------------------------------
// Multi-step IF neuron, float4-vectorized: v += x_t; s = (v>=1); v *= (1-s)
// Per-element fp32 scan order identical to the reference.
// ---------------------------------------------------------------------------
__global__ void if_kernel(const float4* __restrict__ in, float4* __restrict__ out) {
    int idx = blockIdx.x * blockDim.x + threadIdx.x;   // NELEM/4 threads
    float v[4] = {0.f, 0.f, 0.f, 0.f};
#pragma unroll
    for (int t = 0; t < T_STEPS; ++t) {
        float4 x = in[(size_t)t * (NELEM / 4) + idx];
        float s[4];
        v[0] += x.x; v[1] += x.y; v[2] += x.z; v[3] += x.w;
#pragma unroll
        for (int j = 0; j < 4; ++j) {
            s[j] = (v[j] >= 1.0f) ? 1.0f : 0.0f;
            v[j] *= (1.0f - s[j]);
        }
        out[(size_t)t * (NELEM / 4) + idx] = make_float4(s[0], s[1], s[2], s[3]);
    }
}

// ---------------------------------------------------------------------------
// 3x3 conv (pad 1) + BN fused, FFMA2 inner loop.
// Grid: (cog = 0..15, tb = 0..255). Block: 256 threads, 2 CTAs/SM.
// Thread t handles column-pairs (c, c+1) at rows h0 = t>>4 and h0+16,
// accumulating 8 output channels as packed f32x2.
// Double-buffered SMEM: padded 34x34 plane + duplicated-weight float2 table.
// ---------------------------------------------------------------------------
__global__ void __launch_bounds__(256, 2)
conv_bn_kernel(const float* __restrict__ in, const float* __restrict__ wgt,
               const float* __restrict__ gamma, const float* __restrict__ beta,
               const float* __restrict__ mean,  const float* __restrict__ var,
               float* __restrict__ out) {
    __shared__ __align__(16) float  splane[2][34 * 34];
    __shared__ __align__(16) float2 swt2[2][72];

    const int cog    = blockIdx.x;
    const int tb     = blockIdx.y;
    const int cobase = cog * 8;
    const int tid    = threadIdx.x;

    // Zero both buffers once (borders stay zero; interior rewritten per ci).
    for (int i = tid; i < 34 * 34; i += 256) { splane[0][i] = 0.f; splane[1][i] = 0.f; }

    const float* ipbase = in + (size_t)tb * CH * PLANE;
    const int srow = (tid >> 3) + 1;          // staging: padded row 1..32
    const int scol = (tid & 7) * 4 + 1;       // staging: padded col 1..29 (4 wide)

    // Stage ci = 0 into buffer 0.
    {
        float4 r = ((const float4*)ipbase)[tid];
        float* d = &splane[0][srow * 34 + scol];
        d[0] = r.x; d[1] = r.y; d[2] = r.z; d[3] = r.w;
        if (tid < 72) {
            int co = tid / 9, k = tid - co * 9;
            float w = wgt[((size_t)(cobase + co) * CH + 0) * 9 + k];
            swt2[0][tid] = make_float2(w, w);
        }
    }
    __syncthreads();

    ull acc[2][8];
#pragma unroll
    for (int pr = 0; pr < 2; ++pr)
#pragma unroll
        for (int c = 0; c < 8; ++c) acc[pr][c] = 0ull;

    const int h0 = tid >> 4;          // output row for pair 0 (pair 1: h0+16)
    const int c0 = (tid & 15) * 2;    // even output column

    for (int ci = 0; ci < CH; ++ci) {
        const int buf = ci & 1, nbuf = buf ^ 1;

        // Prefetch next plane/weights into registers (latency overlaps compute).
        float4 rnext; float wnext = 0.f;
        const bool more = (ci + 1 < CH);
        if (more) {
            rnext = ((const float4*)(ipbase + (size_t)(ci + 1) * PLANE))[tid];
            if (tid < 72) {
                int co = tid / 9, k = tid - co * 9;
                wnext = wgt[((size_t)(cobase + co) * CH + (ci + 1)) * 9 + k];
            }
        }

        // Window tap-pairs: rows h..h+2, padded cols c0..c0+3 per pair.
        ull A[2][3], Bv[2][3], M[2][3];
#pragma unroll
        for (int pr = 0; pr < 2; ++pr) {
            const int h = h0 + pr * 16;
            const ull* p = (const ull*)&splane[buf][h * 34 + c0];  // 8B-aligned (even idx)
#pragma unroll
            for (int rr = 0; rr < 3; ++rr) {
                A[pr][rr]  = p[rr * 17];        // cols c0,   c0+1
                Bv[pr][rr] = p[rr * 17 + 1];    // cols c0+2, c0+3
                M[pr][rr]  = mid2(A[pr][rr], Bv[pr][rr]);  // cols c0+1, c0+2
            }
        }

        // 8 co x 9 taps x 2 pairs packed FMAs.
        const ull* wp = (const ull*)&swt2[buf][0];
#pragma unroll
        for (int co = 0; co < 8; ++co) {
            ull w0 = wp[co * 9 + 0], w1 = wp[co * 9 + 1], w2 = wp[co * 9 + 2];
            ull w3 = wp[co * 9 + 3], w4 = wp[co * 9 + 4], w5 = wp[co * 9 + 5];
            ull w6 = wp[co * 9 + 6], w7 = wp[co * 9 + 7], w8 = wp[co * 9 + 8];
#pragma unroll
            for (int pr = 0; pr < 2; ++pr) {
                fma2(acc[pr][co], A[pr][0],  w0);
                fma2(acc[pr][co], M[pr][0],  w1);
                fma2(acc[pr][co], Bv[pr][0], w2);
                fma2(acc[pr][co], A[pr][1],  w3);
                fma2(acc[pr][co], M[pr][1],  w4);
                fma2(acc[pr][co], Bv[pr][1], w5);
                fma2(acc[pr][co], A[pr][2],  w6);
                fma2(acc[pr][co], M[pr][2],  w7);
                fma2(acc[pr][co], Bv[pr][2], w8);
            }
        }

        // Commit prefetched data to the other buffer.
        if (more) {
            float* d = &splane[nbuf][srow * 34 + scol];
            d[0] = rnext.x; d[1] = rnext.y; d[2] = rnext.z; d[3] = rnext.w;
            if (tid < 72) swt2[nbuf][tid] = make_float2(wnext, wnext);
        }
        __syncthreads();   // next-buffer writes done AND current-buffer reads done
    }

    // Fused BN epilogue: y*inv + (beta - mean*inv)
#pragma unroll
    for (int co = 0; co < 8; ++co) {
        const int cg  = cobase + co;
        const float inv  = gamma[cg] * rsqrtf(var[cg] + 1e-5f) * 1.0f;
        const float invd = gamma[cg] / sqrtf(var[cg] + 1e-5f);   // match ref exactly
        (void)inv;
        const float bias = beta[cg] - mean[cg] * invd;
        float* op = out + ((size_t)tb * CH + cg) * PLANE;
#pragma unroll
        for (int pr = 0; pr < 2; ++pr) {
            float lo, hi;
            unpk(acc[pr][co], lo, hi);
            const int p = (h0 + pr * 16) * 32 + c0;
            *(float2*)&op[p] = make_float2(lo * invd + bias, hi * invd + bias);
        }
    }
}

// ---------------------------------------------------------------------------
// Pipeline: if1(x)->spk ; conv1(spk)->y ; if2(y)->spk ; conv2(spk)->out
// ---------------------------------------------------------------------------
extern "C" void kernel_launch(void* const* d_in, const int* in_sizes, int n_in,
                              void* d_out, int out_size) {
    const float* x  = (const float*)d_in[0];
    const float* w1 = (const float*)d_in[1];
    const float* g1 = (const float*)d_in[2];
    const float* b1 = (const float*)d_in[3];
    const float* m1 = (const float*)d_in[4];
    const float* v1 = (const float*)d_in[5];
    const float* w2 = (const float*)d_in[6];
    const float* g2 = (const float*)d_in[7];
    const float* b2 = (const float*)d_in[8];
    const float* m2 = (const float*)d_in[9];
    const float* v2 = (const float*)d_in[10];
    float* out = (float*)d_out;

    float *spk = nullptr, *y = nullptr;
    cudaGetSymbolAddress((void**)&spk, g_spk);
    cudaGetSymbolAddress((void**)&y,   g_y);

    const int ifBlocks = (NELEM / 4 + 255) / 256;
    dim3 cgrid(CH / 8, NIMG);   // x = co-group (fast) -> same-image blocks co-resident

    if_kernel<<<ifBlocks, 256>>>((const float4*)x, (float4*)spk);
    conv_bn_kernel<<<cgrid, 256>>>(spk, w1, g1, b1, m1, v1, y);
    if_kernel<<<ifBlocks, 256>>>((const float4*)y, (float4*)spk);
    conv_bn_kernel<<<cgrid, 256>>>(spk, w2, g2, b2, m2, v2, out);
}

// round 7
// speedup vs baseline: 3.0364x; 1.1319x over previous
#include <cuda_runtime.h>
#include <math.h>

// Problem constants: x [T=8, B=32, C=128, H=32, W=32]
#define T_STEPS 8
#define BATCH   32
#define CH      128
#define PLANE   1024                     // 32*32
#define NIMG    (T_STEPS * BATCH)        // 256
#define NELEM   (BATCH * CH * PLANE)     // 4,194,304
#define TOTAL   (T_STEPS * NELEM)        // 33,554,432

typedef unsigned long long ull;

// Scratch ping-pong buffers (no cudaMalloc allowed).
__device__ float g_spk[TOTAL];
__device__ float g_y[TOTAL];

// ---------------------------------------------------------------------------
// Packed fp32x2 helpers (Blackwell FFMA2 — only reachable via PTX)
// ---------------------------------------------------------------------------
__device__ __forceinline__ void fma2(ull& acc, ull a, ull b) {
    asm("fma.rn.f32x2 %0, %1, %2, %0;" : "+l"(acc) : "l"(a), "l"(b));
}
// {a.hi, b.lo} — middle tap pack
__device__ __forceinline__ ull mid2(ull a, ull b) {
    ull r;
    asm("{\n\t"
        ".reg .b32 xa, ya, xb, yb;\n\t"
        "mov.b64 {xa, ya}, %1;\n\t"
        "mov.b64 {xb, yb}, %2;\n\t"
        "mov.b64 %0, {ya, xb};\n\t"
        "}" : "=l"(r) : "l"(a), "l"(b));
    return r;
}
__device__ __forceinline__ void unpk(ull a, float& lo, float& hi) {
    asm("mov.b64 {%0, %1}, %2;" : "=f"(lo), "=f"(hi) : "l"(a));
}

// ---------------------------------------------------------------------------
// Multi-step IF neuron, float4-vectorized: v += x_t; s = (v>=1); v *= (1-s)
// ---------------------------------------------------------------------------
__global__ void if_kernel(const float4* __restrict__ in, float4* __restrict__ out) {
    int idx = blockIdx.x * blockDim.x + threadIdx.x;   // NELEM/4 threads
    float v[4] = {0.f, 0.f, 0.f, 0.f};
#pragma unroll
    for (int t = 0; t < T_STEPS; ++t) {
        float4 x = in[(size_t)t * (NELEM / 4) + idx];
        float s[4];
        v[0] += x.x; v[1] += x.y; v[2] += x.z; v[3] += x.w;
#pragma unroll
        for (int j = 0; j < 4; ++j) {
            s[j] = (v[j] >= 1.0f) ? 1.0f : 0.0f;
            v[j] *= (1.0f - s[j]);
        }
        out[(size_t)t * (NELEM / 4) + idx] = make_float4(s[0], s[1], s[2], s[3]);
    }
}

// ---------------------------------------------------------------------------
// 3x3 conv (pad 1) + BN fused, FFMA2, widened spatial reuse.
// Grid: (cog = 0..15, tb = 0..255). Block: 256 threads, 2 CTAs/SM.
// Thread layout: sp = tid&127 -> 4 consecutive output rows (h0 = (sp>>4)*4)
// at one column-pair (c0 = (sp&15)*2); co-half ch = tid>>7 -> 4 output chans.
// Per ci: 6 shared window rows (12 LDS.64) serve 4 row-pairs; each weight
// LDS.64 feeds 4 FFMA2 (ratio 4:1, was 2:1).
// ---------------------------------------------------------------------------
__global__ void __launch_bounds__(256, 2)
conv_bn_kernel(const float* __restrict__ in, const float* __restrict__ wgt,
               const float* __restrict__ gamma, const float* __restrict__ beta,
               const float* __restrict__ mean,  const float* __restrict__ var,
               float* __restrict__ out) {
    __shared__ __align__(16) float  splane[2][34 * 34];
    __shared__ __align__(16) float2 swt2[2][72];

    const int cobase = blockIdx.x * 8;
    const int tb     = blockIdx.y;
    const int tid    = threadIdx.x;
    const int sp     = tid & 127;
    const int ch     = tid >> 7;            // co-half: 0 or 1
    const int h0     = (sp >> 4) * 4;       // first output row (0,4,...,28)
    const int c0     = (sp & 15) * 2;       // even output column

    // Zero both buffers once (borders stay zero; interior rewritten per ci).
    for (int i = tid; i < 34 * 34; i += 256) { splane[0][i] = 0.f; splane[1][i] = 0.f; }

    const float* ipbase = in + (size_t)tb * CH * PLANE;
    const int srow = (tid >> 3) + 1;        // staging: padded row 1..32
    const int scol = (tid & 7) * 4 + 1;     // staging: padded col 1..29 (4 wide)

    // Stage ci = 0 into buffer 0.
    {
        float4 r = ((const float4*)ipbase)[tid];
        float* d = &splane[0][srow * 34 + scol];
        d[0] = r.x; d[1] = r.y; d[2] = r.z; d[3] = r.w;
        if (tid < 72) {
            int co = tid / 9, k = tid - co * 9;
            float w = wgt[((size_t)(cobase + co) * CH + 0) * 9 + k];
            swt2[0][tid] = make_float2(w, w);
        }
    }
    __syncthreads();

    ull acc[4][4];
#pragma unroll
    for (int pr = 0; pr < 4; ++pr)
#pragma unroll
        for (int c = 0; c < 4; ++c) acc[pr][c] = 0ull;

    for (int ci = 0; ci < CH; ++ci) {
        const int buf = ci & 1, nbuf = buf ^ 1;

        // Prefetch next plane/weights into registers (latency overlaps compute).
        float4 rnext; float wnext = 0.f;
        const bool more = (ci + 1 < CH);
        if (more) {
            rnext = ((const float4*)(ipbase + (size_t)(ci + 1) * PLANE))[tid];
            if (tid < 72) {
                int co = tid / 9, k = tid - co * 9;
                wnext = wgt[((size_t)(cobase + co) * CH + (ci + 1)) * 9 + k];
            }
        }

        // 6 shared window rows (padded rows h0..h0+5) at padded cols c0..c0+3.
        ull A[6], Bv[6], M[6];
        {
            const ull* p = (const ull*)&splane[buf][h0 * 34 + c0];  // 8B aligned
#pragma unroll
            for (int r = 0; r < 6; ++r) {
                A[r]  = p[r * 17];          // cols c0,   c0+1
                Bv[r] = p[r * 17 + 1];      // cols c0+2, c0+3
                M[r]  = mid2(A[r], Bv[r]);  // cols c0+1, c0+2
            }
        }

        // 4 co x 9 taps x 4 row-pairs packed FMAs.
        const ull* wp = (const ull*)&swt2[buf][(ch * 4) * 9];
#pragma unroll
        for (int co = 0; co < 4; ++co) {
            ull w0 = wp[co * 9 + 0], w1 = wp[co * 9 + 1], w2 = wp[co * 9 + 2];
            ull w3 = wp[co * 9 + 3], w4 = wp[co * 9 + 4], w5 = wp[co * 9 + 5];
            ull w6 = wp[co * 9 + 6], w7 = wp[co * 9 + 7], w8 = wp[co * 9 + 8];
#pragma unroll
            for (int pr = 0; pr < 4; ++pr) {
                fma2(acc[pr][co], A[pr + 0],  w0);
                fma2(acc[pr][co], M[pr + 0],  w1);
                fma2(acc[pr][co], Bv[pr + 0], w2);
                fma2(acc[pr][co], A[pr + 1],  w3);
                fma2(acc[pr][co], M[pr + 1],  w4);
                fma2(acc[pr][co], Bv[pr + 1], w5);
                fma2(acc[pr][co], A[pr + 2],  w6);
                fma2(acc[pr][co], M[pr + 2],  w7);
                fma2(acc[pr][co], Bv[pr + 2], w8);
            }
        }

        // Commit prefetched data to the other buffer.
        if (more) {
            float* d = &splane[nbuf][srow * 34 + scol];
            d[0] = rnext.x; d[1] = rnext.y; d[2] = rnext.z; d[3] = rnext.w;
            if (tid < 72) swt2[nbuf][tid] = make_float2(wnext, wnext);
        }
        __syncthreads();   // next-buffer writes done AND current-buffer reads done
    }

    // Fused BN epilogue: y*inv + (beta - mean*inv)
#pragma unroll
    for (int co = 0; co < 4; ++co) {
        const int cg  = cobase + ch * 4 + co;
        const float invd = gamma[cg] / sqrtf(var[cg] + 1e-5f);
        const float bias = beta[cg] - mean[cg] * invd;
        float* op = out + ((size_t)tb * CH + cg) * PLANE;
#pragma unroll
        for (int pr = 0; pr < 4; ++pr) {
            float lo, hi;
            unpk(acc[pr][co], lo, hi);
            *(float2*)&op[(h0 + pr) * 32 + c0] = make_float2(lo * invd + bias, hi * invd + bias);
        }
    }
}

// ---------------------------------------------------------------------------
// Pipeline: if1(x)->spk ; conv1(spk)->y ; if2(y)->spk ; conv2(spk)->out
// ---------------------------------------------------------------------------
extern "C" void kernel_launch(void* const* d_in, const int* in_sizes, int n_in,
                              void* d_out, int out_size) {
    const float* x  = (const float*)d_in[0];
    const float* w1 = (const float*)d_in[1];
    const float* g1 = (const float*)d_in[2];
    const float* b1 = (const float*)d_in[3];
    const float* m1 = (const float*)d_in[4];
    const float* v1 = (const float*)d_in[5];
    const float* w2 = (const float*)d_in[6];
    const float* g2 = (const float*)d_in[7];
    const float* b2 = (const float*)d_in[8];
    const float* m2 = (const float*)d_in[9];
    const float* v2 = (const float*)d_in[10];
    float* out = (float*)d_out;

    float *spk = nullptr, *y = nullptr;
    cudaGetSymbolAddress((void**)&spk, g_spk);
    cudaGetSymbolAddress((void**)&y,   g_y);

    const int ifBlocks = (NELEM / 4 + 255) / 256;
    dim3 cgrid(CH / 8, NIMG);   // x = co-group (fast) -> same-image blocks co-resident

    if_kernel<<<ifBlocks, 256>>>((const float4*)x, (float4*)spk);
    conv_bn_kernel<<<cgrid, 256>>>(spk, w1, g1, b1, m1, v1, y);
    if_kernel<<<ifBlocks, 256>>>((const float4*)y, (float4*)spk);
    conv_bn_kernel<<<cgrid, 256>>>(spk, w2, g2, b2, m2, v2, out);
}

// round 8
// speedup vs baseline: 3.2973x; 1.0859x over previous
#include <cuda_runtime.h>
#include <math.h>

// Problem constants: x [T=8, B=32, C=128, H=32, W=32]
#define T_STEPS 8
#define BATCH   32
#define CH      128
#define PLANE   1024                     // 32*32
#define NIMG    (T_STEPS * BATCH)        // 256
#define NELEM   (BATCH * CH * PLANE)     // 4,194,304
#define TOTAL   (T_STEPS * NELEM)        // 33,554,432
#define SRS     36                       // padded-plane row stride (floats)

typedef unsigned long long ull;

// Scratch ping-pong buffers (no cudaMalloc allowed).
__device__ float g_spk[TOTAL];
__device__ float g_y[TOTAL];

// Packed fp32x2 FMA (Blackwell FFMA2 — only reachable via PTX).
__device__ __forceinline__ void fma2(ull& acc, ull a, ull b) {
    asm("fma.rn.f32x2 %0, %1, %2, %0;" : "+l"(acc) : "l"(a), "l"(b));
}
__device__ __forceinline__ void unpk(ull a, float& lo, float& hi) {
    asm("mov.b64 {%0, %1}, %2;" : "=f"(lo), "=f"(hi) : "l"(a));
}

// ---------------------------------------------------------------------------
// Multi-step IF neuron, float4-vectorized: v += x_t; s = (v>=1); v *= (1-s)
// ---------------------------------------------------------------------------
__global__ void if_kernel(const float4* __restrict__ in, float4* __restrict__ out) {
    int idx = blockIdx.x * blockDim.x + threadIdx.x;   // NELEM/4 threads
    float v[4] = {0.f, 0.f, 0.f, 0.f};
#pragma unroll
    for (int t = 0; t < T_STEPS; ++t) {
        float4 x = in[(size_t)t * (NELEM / 4) + idx];
        float s[4];
        v[0] += x.x; v[1] += x.y; v[2] += x.z; v[3] += x.w;
#pragma unroll
        for (int j = 0; j < 4; ++j) {
            s[j] = (v[j] >= 1.0f) ? 1.0f : 0.0f;
            v[j] *= (1.0f - s[j]);
        }
        out[(size_t)t * (NELEM / 4) + idx] = make_float4(s[0], s[1], s[2], s[3]);
    }
}

// ---------------------------------------------------------------------------
// 3x3 conv (pad 1) + BN fused, FFMA2.
// Grid: (cog, tb). Block 256, 2 CTAs/SM.
// Dual shifted SMEM copies: P0[j]=padded[j], P1[j]=padded[j+1] -> all three
// horizontal tap-pairs are aligned LDS.64 (no repack MOVs).
// 2 input channels per buffer -> 64 barriers. Weights padded to 80B/co for
// LDS.128 broadcast loads.
// ---------------------------------------------------------------------------
__global__ void __launch_bounds__(256, 2)
conv_bn_kernel(const float* __restrict__ in, const float* __restrict__ wgt,
               const float* __restrict__ gamma, const float* __restrict__ beta,
               const float* __restrict__ mean,  const float* __restrict__ var,
               float* __restrict__ out) {
    __shared__ __align__(16) float  sP0[2][2][34 * SRS];   // [buf][slot]
    __shared__ __align__(16) float  sP1[2][2][34 * SRS];
    __shared__ __align__(16) float2 swt[2][2][8][10];      // [buf][slot][co][tap(9)+pad]

    const int cobase = blockIdx.x * 8;
    const int tb     = blockIdx.y;
    const int tid    = threadIdx.x;
    const int sp     = tid & 127;
    const int ch     = tid >> 7;            // co-half: 0 or 1
    const int h0     = (sp >> 4) * 4;       // first output row (0,4,...,28)
    const int c0     = (sp & 15) * 2;       // even output column
    const int srow   = (tid >> 3) + 1;      // staging padded row 1..32
    const int scol4  = (tid & 7) * 4;       // staging input col base 0,4,...,28

    // Zero both plane arrays once (borders must be 0).
    for (int i = tid; i < 2 * 2 * 34 * SRS; i += 256) {
        ((float*)sP0)[i] = 0.f;
        ((float*)sP1)[i] = 0.f;
    }
    __syncthreads();

    const float* ipbase = in + (size_t)tb * CH * PLANE;

    // Stage ci = 0,1 into buffer 0.
#pragma unroll
    for (int s = 0; s < 2; ++s) {
        float4 v = ((const float4*)(ipbase + (size_t)s * PLANE))[tid];
        float* p0 = &sP0[0][s][srow * SRS + scol4 + 1];   // P0[j] = padded[j]
        p0[0] = v.x; p0[1] = v.y; p0[2] = v.z; p0[3] = v.w;
        *(float4*)&sP1[0][s][srow * SRS + scol4] = v;     // P1[j] = padded[j+1]
    }
    if (tid < 144) {
        int s = (tid >= 72) ? 1 : 0, id = tid - 72 * s;
        int co = id / 9, k = id - co * 9;
        float w = wgt[((size_t)(cobase + co) * CH + s) * 9 + k];
        swt[0][s][co][k] = make_float2(w, w);
    }
    __syncthreads();

    ull acc[4][4];
#pragma unroll
    for (int pr = 0; pr < 4; ++pr)
#pragma unroll
        for (int c = 0; c < 4; ++c) acc[pr][c] = 0ull;

    const int bi = (h0 * SRS + c0) >> 1;    // ull index of window base

    for (int it = 0; it < 64; ++it) {
        const int buf = it & 1;

        // Prefetch next channel pair (latency overlaps compute below).
        float4 vn0, vn1; float wn = 0.f;
        const bool more = (it < 63);
        if (more) {
            const float* np = ipbase + (size_t)(it * 2 + 2) * PLANE;
            vn0 = ((const float4*)np)[tid];
            vn1 = ((const float4*)(np + PLANE))[tid];
            if (tid < 144) {
                int s = (tid >= 72) ? 1 : 0, id = tid - 72 * s;
                int co = id / 9, k = id - co * 9;
                wn = wgt[((size_t)(cobase + co) * CH + (it * 2 + 2 + s)) * 9 + k];
            }
        }

#pragma unroll
        for (int s = 0; s < 2; ++s) {
            const ull* P0 = (const ull*)sP0[buf][s];
            const ull* P1 = (const ull*)sP1[buf][s];
            ull A[6], Bv[6], M[6];
#pragma unroll
            for (int r = 0; r < 6; ++r) {
                A[r]  = P0[bi + r * (SRS / 2)];       // cols c0,   c0+1
                Bv[r] = P0[bi + r * (SRS / 2) + 1];   // cols c0+2, c0+3
                M[r]  = P1[bi + r * (SRS / 2)];       // cols c0+1, c0+2
            }
            const float2* wbase = &swt[buf][s][ch * 4][0];
#pragma unroll
            for (int co = 0; co < 4; ++co) {
                const ulonglong2* wq = (const ulonglong2*)(wbase + (size_t)co * 10);
                ulonglong2 q0 = wq[0], q1 = wq[1], q2 = wq[2], q3 = wq[3];
                ull w8 = *(const ull*)(wbase + (size_t)co * 10 + 8);
#pragma unroll
                for (int pr = 0; pr < 4; ++pr) {
                    fma2(acc[pr][co], A[pr + 0],  q0.x);
                    fma2(acc[pr][co], M[pr + 0],  q0.y);
                    fma2(acc[pr][co], Bv[pr + 0], q1.x);
                    fma2(acc[pr][co], A[pr + 1],  q1.y);
                    fma2(acc[pr][co], M[pr + 1],  q2.x);
                    fma2(acc[pr][co], Bv[pr + 1], q2.y);
                    fma2(acc[pr][co], A[pr + 2],  q3.x);
                    fma2(acc[pr][co], M[pr + 2],  q3.y);
                    fma2(acc[pr][co], Bv[pr + 2], w8);
                }
            }
        }

        // Commit prefetched pair to the other buffer.
        if (more) {
            const int nb = buf ^ 1;
            {
                float* p0 = &sP0[nb][0][srow * SRS + scol4 + 1];
                p0[0] = vn0.x; p0[1] = vn0.y; p0[2] = vn0.z; p0[3] = vn0.w;
                *(float4*)&sP1[nb][0][srow * SRS + scol4] = vn0;
            }
            {
                float* p0 = &sP0[nb][1][srow * SRS + scol4 + 1];
                p0[0] = vn1.x; p0[1] = vn1.y; p0[2] = vn1.z; p0[3] = vn1.w;
                *(float4*)&sP1[nb][1][srow * SRS + scol4] = vn1;
            }
            if (tid < 144) {
                int s = (tid >= 72) ? 1 : 0, id = tid - 72 * s;
                int co = id / 9, k = id - co * 9;
                swt[nb][s][co][k] = make_float2(wn, wn);
            }
        }
        __syncthreads();
    }

    // Fused BN epilogue: y*inv + (beta - mean*inv)
#pragma unroll
    for (int co = 0; co < 4; ++co) {
        const int cg  = cobase + ch * 4 + co;
        const float invd = gamma[cg] / sqrtf(var[cg] + 1e-5f);
        const float bias = beta[cg] - mean[cg] * invd;
        float* op = out + ((size_t)tb * CH + cg) * PLANE;
#pragma unroll
        for (int pr = 0; pr < 4; ++pr) {
            float lo, hi;
            unpk(acc[pr][co], lo, hi);
            *(float2*)&op[(h0 + pr) * 32 + c0] = make_float2(lo * invd + bias, hi * invd + bias);
        }
    }
}

// ---------------------------------------------------------------------------
// Pipeline: if1(x)->spk ; conv1(spk)->y ; if2(y)->spk ; conv2(spk)->out
// ---------------------------------------------------------------------------
extern "C" void kernel_launch(void* const* d_in, const int* in_sizes, int n_in,
                              void* d_out, int out_size) {
    const float* x  = (const float*)d_in[0];
    const float* w1 = (const float*)d_in[1];
    const float* g1 = (const float*)d_in[2];
    const float* b1 = (const float*)d_in[3];
    const float* m1 = (const float*)d_in[4];
    const float* v1 = (const float*)d_in[5];
    const float* w2 = (const float*)d_in[6];
    const float* g2 = (const float*)d_in[7];
    const float* b2 = (const float*)d_in[8];
    const float* m2 = (const float*)d_in[9];
    const float* v2 = (const float*)d_in[10];
    float* out = (float*)d_out;

    float *spk = nullptr, *y = nullptr;
    cudaGetSymbolAddress((void**)&spk, g_spk);
    cudaGetSymbolAddress((void**)&y,   g_y);

    const int ifBlocks = (NELEM / 4 + 255) / 256;
    dim3 cgrid(CH / 8, NIMG);   // co-group fast -> same-image blocks co-resident

    if_kernel<<<ifBlocks, 256>>>((const float4*)x, (float4*)spk);
    conv_bn_kernel<<<cgrid, 256>>>(spk, w1, g1, b1, m1, v1, y);
    if_kernel<<<ifBlocks, 256>>>((const float4*)y, (float4*)spk);
    conv_bn_kernel<<<cgrid, 256>>>(spk, w2, g2, b2, m2, v2, out);
}